// round 12
// baseline (speedup 1.0000x reference)
#include <cuda_runtime.h>
#include <cstdint>

#define D     128
#define NN    512
#define BB    4
#define ROWS  16      // rows per block
#define NPROD 56u     // fold producer blocks (7 jobs x 8 f-chunks)
#define NBLK  128u    // one block per SM (128 < 148) -> no wave imbalance
#define BPB   32u     // blocks per batch
#define NT    512     // threads per block (16 warps/SM)

// Scratch (device globals — no allocation allowed)
__device__ float g_part[56 * D];       // W1 fold partials
__device__ float g_r[BB * NN * 4];     // per row: li0 li1 lj0 lj1
__device__ unsigned g_ready = 0u;      // fold completion counter
__device__ unsigned g_batch[BB] = {0u, 0u, 0u, 0u};  // per-batch completion
__device__ unsigned g_done  = 0u;      // completion ticket (reset for next replay)

// smem floats: W2 16384 | h 2048 | Hf 2048 | Wc 512 | p 16   (~84KB)
#define OFF_W2 0
#define OFF_H  16384
#define OFF_HF (16384 + 2048)
#define OFF_WC (16384 + 2048 + 2048)
#define OFF_P  (16384 + 2048 + 2048 + 512)
#define SMEM_FLOATS (16384 + 2048 + 2048 + 512 + 16)

// ---------------------------------------------------------------------------
// ONE kernel, 128 blocks x 512 threads:
//   fold (blocks 0..55) --g_ready--> 16-row MLP --g_batch[b]--> expand.
// ---------------------------------------------------------------------------
__global__ void __launch_bounds__(NT, 1)
fused_kernel(const int*   __restrict__ adj,
             const int*   __restrict__ t,
             const float* __restrict__ TE,
             const float* __restrict__ nc,
             const float* __restrict__ EE,
             const float* __restrict__ W1,
             const float* __restrict__ b1,
             const float* __restrict__ W2,
             const float* __restrict__ b2,
             const float* __restrict__ Wc,
             const float* __restrict__ bc,
             float*       __restrict__ out)
{
    extern __shared__ float smem[];
    float* W2s = smem + OFF_W2;   // [d][128]
    float* h_s = smem + OFF_H;    // [d][16]
    float* Hfs = smem + OFF_HF;   // [r][128]
    float* Wcs = smem + OFF_WC;   // [e][4]
    float* p_s = smem + OFF_P;    // [16]

    const int tid   = threadIdx.x;
    const int bid   = blockIdx.x;
    const int b     = bid >> 5;            // batch (32 blocks per batch)
    const int i0    = (bid & 31) * ROWS;
    const int grow0 = b * NN + i0;

    const int warp = tid >> 5;             // 0..15
    const int lane = tid & 31;
    const int e    = tid & 127;            // output column / hidden dim
    const int g    = tid >> 7;             // 0..3: 4-row group

    // ---- producer role: W1 fold chunk (blocks 0..55) ----
    if (bid < (int)NPROD) {
        __shared__ float s_coef[16];
        const int j  = bid >> 3;           // 0..6
        const int f0 = (bid & 7) * 16;
        if (tid < 16) {
            int f = f0 + tid;
            float v;
            if (j == 0)      v = EE[D + f] - EE[f];
            else if (j == 1) v = EE[f];
            else if (j == 2) v = nc[f];
            else             v = TE[(size_t)t[j - 3] * D + f];
            s_coef[tid] = v;
        }
        __syncthreads();
        if (tid < 128) {
            const int blk = (j <= 1) ? 0 : (j == 2 ? 1 : 2);
            const float* W = W1 + ((size_t)blk * D + f0) * D + tid;
            float acc = 0.f;
#pragma unroll
            for (int f = 0; f < 16; f++)
                acc = fmaf(s_coef[f], W[(size_t)f * D], acc);
            g_part[bid * D + tid] = acc;
            __threadfence();               // release g_part
        }
        __syncthreads();
        if (tid == 0) atomicAdd(&g_ready, 1u);
    }

    // ---- prologue (independent of fold) ----
    // Stage full W2 (64KB): 8 float4 per thread, coalesced.
    {
        const float4* W2_4 = (const float4*)W2;
        float4* W2s_4 = (float4*)W2s;
#pragma unroll
        for (int k = 0; k < 8; k++) W2s_4[tid + k * NT] = W2_4[tid + k * NT];
    }
    if (tid < 128) {
        float4 wc = make_float4(Wc[tid * 2 + 0], Wc[tid * 2 + 1],
                                Wc[(D + tid) * 2 + 0], Wc[(D + tid) * 2 + 1]);
        *(float4*)(Wcs + tid * 4) = wc;
    }
    const float b2e = b2[e];
    const float bc0 = bc[0], bc1 = bc[1];

    // p: warp w reduces row w (512 ints = 128 int4, 4 per lane, DRAM)
    {
        const int4* a4 = (const int4*)adj + (size_t)(grow0 + warp) * (NN / 4);
        int s = 0;
#pragma unroll
        for (int k = 0; k < 4; k++) {
            int4 v = a4[k * 32 + lane];
            s += v.x + v.y + v.z + v.w;
        }
#pragma unroll
        for (int o = 16; o; o >>= 1) s += __shfl_xor_sync(0xffffffffu, s, o);
        if (lane == 0) p_s[warp] = (float)s * (1.0f / 512.0f);
    }

    // ---- wait for fold completion (near-zero: fold << prologue) ----
    if (tid == 0) {
        while (*(volatile unsigned*)&g_ready < NPROD) __nanosleep(32);
        __threadfence();                   // acquire
    }
    __syncthreads();

    // Finalize v1/base at hidden dim d=e; thread group g builds h for 4 rows.
    {
        float v1d   = 0.f;
        float based = b1[e];
#pragma unroll
        for (int c = 0; c < 8; c++) {
            v1d   += g_part[(0 * 8 + c) * D + e];
            based += g_part[(1 * 8 + c) * D + e]
                   + g_part[(2 * 8 + c) * D + e]
                   + g_part[((3 + b) * 8 + c) * D + e];
        }
        float4 pr = *(const float4*)(p_s + 4 * g);
        float4 hv;
        hv.x = fmaxf(fmaf(pr.x, v1d, based), 0.f);
        hv.y = fmaxf(fmaf(pr.y, v1d, based), 0.f);
        hv.z = fmaxf(fmaf(pr.z, v1d, based), 0.f);
        hv.w = fmaxf(fmaf(pr.w, v1d, based), 0.f);
        *(float4*)(h_s + e * ROWS + g * 4) = hv;
    }
    __syncthreads();

    // Matvec: thread (e, g) computes Hf[r][e] for 4 rows via f32x2 (2 accs).
    unsigned long long acc0, acc1;
    {
        unsigned int ub = __float_as_uint(b2e);
        asm("mov.b64 %0, {%1, %1};" : "=l"(acc0) : "r"(ub));
        acc1 = acc0;
    }
#pragma unroll 16
    for (int d = 0; d < D; d++) {
        float w = W2s[d * D + e];
        ulonglong2 hh = *(const ulonglong2*)(h_s + d * ROWS + g * 4); // warp-uniform bcast
        unsigned long long w2;
        asm("mov.b64 %0, {%1, %1};" : "=l"(w2) : "r"(__float_as_uint(w)));
        asm("fma.rn.f32x2 %0, %1, %2, %0;" : "+l"(acc0) : "l"(w2), "l"(hh.x));
        asm("fma.rn.f32x2 %0, %1, %2, %0;" : "+l"(acc1) : "l"(w2), "l"(hh.y));
    }
    {
        float2 f0 = *(float2*)&acc0;
        float2 f1 = *(float2*)&acc1;
        Hfs[(g * 4 + 0) * D + e] = fmaxf(f0.x, 0.f);
        Hfs[(g * 4 + 1) * D + e] = fmaxf(f0.y, 0.f);
        Hfs[(g * 4 + 2) * D + e] = fmaxf(f1.x, 0.f);
        Hfs[(g * 4 + 3) * D + e] = fmaxf(f1.y, 0.f);
    }
    __syncthreads();

    // Reduce: warp w handles row w; 4 dots over 128 cols.
    {
        float s0 = 0.f, s1 = 0.f, s2 = 0.f, s3 = 0.f;
#pragma unroll
        for (int k = 0; k < 4; k++) {
            int ee = lane + 32 * k;
            float hv = Hfs[warp * D + ee];
            float4 wc = *(const float4*)(Wcs + ee * 4);
            s0 = fmaf(hv, wc.x, s0);
            s1 = fmaf(hv, wc.y, s1);
            s2 = fmaf(hv, wc.z, s2);
            s3 = fmaf(hv, wc.w, s3);
        }
#pragma unroll
        for (int o = 16; o; o >>= 1) {
            s0 += __shfl_xor_sync(0xffffffffu, s0, o);
            s1 += __shfl_xor_sync(0xffffffffu, s1, o);
            s2 += __shfl_xor_sync(0xffffffffu, s2, o);
            s3 += __shfl_xor_sync(0xffffffffu, s3, o);
        }
        if (lane == 0)
            *(float4*)(g_r + (size_t)(grow0 + warp) * 4) = make_float4(s0, s1, s2, s3);
    }
    __syncthreads();
    if (tid == 0) {
        __threadfence();                   // release g_r writes
        atomicAdd(&g_batch[b], 1u);
    }

    // ---- wait for own batch's 32 blocks (tight: same wave start) ----
    if (tid == 0) {
        while (*(volatile unsigned*)&g_batch[b] < BPB) __nanosleep(32);
        __threadfence();                   // acquire
    }
    __syncthreads();

    // ---- expand: 16 output rows (64KB float4 stores, 8 per thread) ----
    float2* lj_s = (float2*)W2s;           // reuse dead W2 smem
    {
        float2 lj = *(const float2*)(g_r + (size_t)(b * NN + tid) * 4 + 2);
        lj_s[tid] = make_float2(lj.x + bc0, lj.y + bc1);
    }
    __syncthreads();

    float4* out4 = (float4*)out;
    const int jj  = tid & 255;             // output column pair
    const int rh2 = tid >> 8;              // 0/1: row half
    const float4 a = *(const float4*)(lj_s + 2 * jj);  // (ljx0,ljy0,ljx1,ljy1)
#pragma unroll
    for (int r = 0; r < 8; r++) {
        int row = grow0 + rh2 * 8 + r;
        float2 li = *(const float2*)(g_r + (size_t)row * 4);
        out4[(size_t)row * 256 + jj] =
            make_float4(li.x + a.x, li.y + a.y, li.x + a.z, li.y + a.w);
    }

    // ---- completion ticket: last block resets flags for next replay ----
    __syncthreads();
    if (tid == 0) {
        __threadfence();
        unsigned tk = atomicAdd(&g_done, 1u);
        if (tk == NBLK - 1u) {
            g_ready = 0u;
            g_batch[0] = 0u; g_batch[1] = 0u; g_batch[2] = 0u; g_batch[3] = 0u;
            g_done = 0u;
            __threadfence();
        }
    }
}

// ---------------------------------------------------------------------------
extern "C" void kernel_launch(void* const* d_in, const int* in_sizes, int n_in,
                              void* d_out, int out_size)
{
    const int*   adj = (const int*)d_in[0];
    const int*   t   = (const int*)d_in[1];
    const float* TE  = (const float*)d_in[2];
    const float* nc  = (const float*)d_in[3];
    const float* EE  = (const float*)d_in[4];
    const float* W1  = (const float*)d_in[5];
    const float* b1  = (const float*)d_in[6];
    const float* W2  = (const float*)d_in[7];
    const float* b2  = (const float*)d_in[8];
    const float* Wc  = (const float*)d_in[9];
    const float* bc  = (const float*)d_in[10];
    float* out = (float*)d_out;

    (void)in_sizes; (void)n_in; (void)out_size;

    const int smem_b = SMEM_FLOATS * sizeof(float);
    cudaFuncSetAttribute(fused_kernel, cudaFuncAttributeMaxDynamicSharedMemorySize, smem_b);

    fused_kernel<<<NBLK, NT, smem_b>>>(adj, t, TE, nc, EE, W1, b1, W2, b2, Wc, bc, out);
}

// round 13
// speedup vs baseline: 1.0979x; 1.0979x over previous
#include <cuda_runtime.h>
#include <cstdint>

#define D     128
#define NN    512
#define BB    4
#define ROWS  16      // rows per block
#define NPROD 56u     // fold producer count (7 jobs x 8 f-chunks)
#define NBLK  128u    // one block per SM -> no wave imbalance
#define BPB   32u     // blocks per batch

// Scratch (device globals — no allocation allowed)
__device__ float g_part[56 * D];       // W1 fold partials (indexed by pid)
__device__ float g_r[BB * NN * 4];     // per row: li0 li1 lj0 lj1
__device__ unsigned g_ready = 0u;      // fold completion counter
__device__ unsigned g_batch[BB] = {0u, 0u, 0u, 0u};  // per-batch completion
__device__ unsigned g_done  = 0u;      // completion ticket (reset for next replay)

// smem floats: W2 16384 | h 2048 | Hf 2048 | Wc 512 | p 16 | li 32  (~84KB)
#define OFF_W2 0
#define OFF_H  16384
#define OFF_HF (16384 + 2048)
#define OFF_WC (16384 + 2048 + 2048)
#define OFF_P  (16384 + 2048 + 2048 + 512)
#define OFF_LI (16384 + 2048 + 2048 + 512 + 16)
#define SMEM_FLOATS (16384 + 2048 + 2048 + 512 + 16 + 32)

// ---------------------------------------------------------------------------
// ONE kernel, 128 blocks x 256 threads. Phase order tuned for critical path:
//   adj loads (DRAM, hoisted) -> fold (even bids < 112: 14 producers/batch)
//   -> W2/Wc staging -> fold-wait -> h -> matvec -> reduce
//   -> batch-wait -> register-path expand (no smem staging).
// ---------------------------------------------------------------------------
__global__ void __launch_bounds__(256, 2)
fused_kernel(const int*   __restrict__ adj,
             const int*   __restrict__ t,
             const float* __restrict__ TE,
             const float* __restrict__ nc,
             const float* __restrict__ EE,
             const float* __restrict__ W1,
             const float* __restrict__ b1,
             const float* __restrict__ W2,
             const float* __restrict__ b2,
             const float* __restrict__ Wc,
             const float* __restrict__ bc,
             float*       __restrict__ out)
{
    extern __shared__ float smem[];
    float* W2s  = smem + OFF_W2;   // [d][128]
    float* h_s  = smem + OFF_H;    // [d][16]
    float* Hfs  = smem + OFF_HF;   // [r][128]
    float* Wcs  = smem + OFF_WC;   // [e][4]
    float* p_s  = smem + OFF_P;    // [16]
    float* li_s = smem + OFF_LI;   // [16][2]

    const int tid   = threadIdx.x;
    const int bid   = blockIdx.x;
    const int b     = bid >> 5;            // batch (32 blocks per batch)
    const int i0    = (bid & 31) * ROWS;
    const int grow0 = b * NN + i0;

    const int warp = tid >> 5;             // 0..7
    const int lane = tid & 31;
    const int e    = tid & 127;            // output column / hidden dim
    const int g    = tid >> 7;             // 0/1: 8-row half

    // ---- adj first: longest-latency DRAM loads, fully hoisted ----
    // warp w handles rows 2w, 2w+1 (each 512 ints = 128 int4).
    {
#pragma unroll
        for (int rr = 0; rr < 2; rr++) {
            int row = 2 * warp + rr;
            const int4* a4 = (const int4*)adj + (size_t)(grow0 + row) * (NN / 4);
            int s = 0;
#pragma unroll
            for (int k = 0; k < 4; k++) {
                int4 v = a4[k * 32 + lane];
                s += v.x + v.y + v.z + v.w;
            }
#pragma unroll
            for (int o = 16; o; o >>= 1) s += __shfl_xor_sync(0xffffffffu, s, o);
            if (lane == 0) p_s[row] = (float)s * (1.0f / 512.0f);
        }
    }

    // ---- producer role: even bids < 112 (14 per batch -> uniform straggler) ----
    if ((bid & 1) == 0 && bid < 112) {
        const int pid = bid >> 1;          // 0..55
        __shared__ float s_coef[16];
        const int j  = pid >> 3;           // 0..6
        const int f0 = (pid & 7) * 16;
        if (tid < 16) {
            int f = f0 + tid;
            float v;
            if (j == 0)      v = EE[D + f] - EE[f];
            else if (j == 1) v = EE[f];
            else if (j == 2) v = nc[f];
            else             v = TE[(size_t)t[j - 3] * D + f];
            s_coef[tid] = v;
        }
        __syncthreads();
        if (tid < 128) {
            const int blk = (j <= 1) ? 0 : (j == 2 ? 1 : 2);
            const float* W = W1 + ((size_t)blk * D + f0) * D + tid;
            float acc = 0.f;
#pragma unroll
            for (int f = 0; f < 16; f++)
                acc = fmaf(s_coef[f], W[(size_t)f * D], acc);
            g_part[pid * D + tid] = acc;
            __threadfence();               // release g_part
        }
        __syncthreads();
        if (tid == 0) atomicAdd(&g_ready, 1u);
    }

    // ---- stage full W2 (64KB, coalesced float4) ----
    {
        const float4* W2_4 = (const float4*)W2;
        float4* W2s_4 = (float4*)W2s;
#pragma unroll
        for (int k = 0; k < 16; k++) W2s_4[tid + k * 256] = W2_4[tid + k * 256];
    }
    if (g == 0) {
        float4 wc = make_float4(Wc[e * 2 + 0], Wc[e * 2 + 1],
                                Wc[(D + e) * 2 + 0], Wc[(D + e) * 2 + 1]);
        *(float4*)(Wcs + e * 4) = wc;
    }
    const float b2e = b2[e];
    const float bc0 = bc[0], bc1 = bc[1];

    // ---- wait for fold completion ----
    if (tid == 0) {
        while (*(volatile unsigned*)&g_ready < NPROD) __nanosleep(32);
        __threadfence();                   // acquire
    }
    __syncthreads();

    // Finalize v1/base at hidden dim d=e; build h[r][d] for 8 rows (half g).
    {
        float v1d   = 0.f;
        float based = b1[e];
#pragma unroll
        for (int c = 0; c < 8; c++) {
            v1d   += g_part[(0 * 8 + c) * D + e];
            based += g_part[(1 * 8 + c) * D + e]
                   + g_part[(2 * 8 + c) * D + e]
                   + g_part[((3 + b) * 8 + c) * D + e];
        }
        float hv[8];
#pragma unroll
        for (int r = 0; r < 8; r++)
            hv[r] = fmaxf(fmaf(p_s[g * 8 + r], v1d, based), 0.f);
        float4* dst = (float4*)(h_s + e * ROWS + g * 8);
        dst[0] = make_float4(hv[0], hv[1], hv[2], hv[3]);
        dst[1] = make_float4(hv[4], hv[5], hv[6], hv[7]);
    }
    __syncthreads();

    // Matvec: thread (e,g) computes Hf[r][e] for its 8 rows via f32x2.
    unsigned long long acc0, acc1, acc2, acc3;
    {
        unsigned int ub = __float_as_uint(b2e);
        asm("mov.b64 %0, {%1, %1};" : "=l"(acc0) : "r"(ub));
        acc1 = acc0; acc2 = acc0; acc3 = acc0;
    }
#pragma unroll 8
    for (int d = 0; d < D; d++) {
        float w = W2s[d * D + e];
        const ulonglong2* hp = (const ulonglong2*)(h_s + d * ROWS + g * 8); // uniform
        ulonglong2 ha = hp[0];
        ulonglong2 hb = hp[1];
        unsigned long long w2;
        asm("mov.b64 %0, {%1, %1};" : "=l"(w2) : "r"(__float_as_uint(w)));
        asm("fma.rn.f32x2 %0, %1, %2, %0;" : "+l"(acc0) : "l"(w2), "l"(ha.x));
        asm("fma.rn.f32x2 %0, %1, %2, %0;" : "+l"(acc1) : "l"(w2), "l"(ha.y));
        asm("fma.rn.f32x2 %0, %1, %2, %0;" : "+l"(acc2) : "l"(w2), "l"(hb.x));
        asm("fma.rn.f32x2 %0, %1, %2, %0;" : "+l"(acc3) : "l"(w2), "l"(hb.y));
    }
    {
        float2 f0 = *(float2*)&acc0;
        float2 f1 = *(float2*)&acc1;
        float2 f2 = *(float2*)&acc2;
        float2 f3 = *(float2*)&acc3;
        Hfs[(g * 8 + 0) * D + e] = fmaxf(f0.x, 0.f);
        Hfs[(g * 8 + 1) * D + e] = fmaxf(f0.y, 0.f);
        Hfs[(g * 8 + 2) * D + e] = fmaxf(f1.x, 0.f);
        Hfs[(g * 8 + 3) * D + e] = fmaxf(f1.y, 0.f);
        Hfs[(g * 8 + 4) * D + e] = fmaxf(f2.x, 0.f);
        Hfs[(g * 8 + 5) * D + e] = fmaxf(f2.y, 0.f);
        Hfs[(g * 8 + 6) * D + e] = fmaxf(f3.x, 0.f);
        Hfs[(g * 8 + 7) * D + e] = fmaxf(f3.y, 0.f);
    }
    __syncthreads();

    // Reduce: warp w -> rows 2w, 2w+1; keep own li in smem for expand.
    {
#pragma unroll
        for (int rr = 0; rr < 2; rr++) {
            int r = 2 * warp + rr;
            float s0 = 0.f, s1 = 0.f, s2 = 0.f, s3 = 0.f;
#pragma unroll
            for (int k = 0; k < 4; k++) {
                int ee = lane + 32 * k;
                float hv = Hfs[r * D + ee];
                float4 wc = *(const float4*)(Wcs + ee * 4);
                s0 = fmaf(hv, wc.x, s0);
                s1 = fmaf(hv, wc.y, s1);
                s2 = fmaf(hv, wc.z, s2);
                s3 = fmaf(hv, wc.w, s3);
            }
#pragma unroll
            for (int o = 16; o; o >>= 1) {
                s0 += __shfl_xor_sync(0xffffffffu, s0, o);
                s1 += __shfl_xor_sync(0xffffffffu, s1, o);
                s2 += __shfl_xor_sync(0xffffffffu, s2, o);
                s3 += __shfl_xor_sync(0xffffffffu, s3, o);
            }
            if (lane == 0) {
                *(float4*)(g_r + (size_t)(grow0 + r) * 4) = make_float4(s0, s1, s2, s3);
                *(float2*)(li_s + r * 2) = make_float2(s0, s1);
            }
        }
    }
    __syncthreads();
    if (tid == 0) {
        __threadfence();                   // release g_r writes
        atomicAdd(&g_batch[b], 1u);
    }

    // ---- wait for own batch's 32 blocks (uniform straggler profile) ----
    if (tid == 0) {
        while (*(volatile unsigned*)&g_batch[b] < BPB) __nanosleep(32);
        __threadfence();                   // acquire
    }
    __syncthreads();

    // ---- expand (register path): thread tid owns column pair 2tid, 2tid+1 ----
    {
        const size_t jbase = (size_t)(b * NN + 2 * tid) * 4 + 2;
        float2 ljA = *(const float2*)(g_r + jbase);       // lj of col 2tid
        float2 ljB = *(const float2*)(g_r + jbase + 4);   // lj of col 2tid+1
        const float ax = ljA.x + bc0, ay = ljA.y + bc1;
        const float az = ljB.x + bc0, aw = ljB.y + bc1;

        float4* out4 = (float4*)out;
#pragma unroll
        for (int r = 0; r < ROWS; r++) {
            float2 li = *(const float2*)(li_s + r * 2);
            out4[(size_t)(grow0 + r) * 256 + tid] =
                make_float4(li.x + ax, li.y + ay, li.x + az, li.y + aw);
        }
    }

    // ---- completion ticket: last block resets flags for next replay ----
    __syncthreads();
    if (tid == 0) {
        __threadfence();
        unsigned tk = atomicAdd(&g_done, 1u);
        if (tk == NBLK - 1u) {
            g_ready = 0u;
            g_batch[0] = 0u; g_batch[1] = 0u; g_batch[2] = 0u; g_batch[3] = 0u;
            g_done = 0u;
            __threadfence();
        }
    }
}

// ---------------------------------------------------------------------------
extern "C" void kernel_launch(void* const* d_in, const int* in_sizes, int n_in,
                              void* d_out, int out_size)
{
    const int*   adj = (const int*)d_in[0];
    const int*   t   = (const int*)d_in[1];
    const float* TE  = (const float*)d_in[2];
    const float* nc  = (const float*)d_in[3];
    const float* EE  = (const float*)d_in[4];
    const float* W1  = (const float*)d_in[5];
    const float* b1  = (const float*)d_in[6];
    const float* W2  = (const float*)d_in[7];
    const float* b2  = (const float*)d_in[8];
    const float* Wc  = (const float*)d_in[9];
    const float* bc  = (const float*)d_in[10];
    float* out = (float*)d_out;

    (void)in_sizes; (void)n_in; (void)out_size;

    const int smem_b = SMEM_FLOATS * sizeof(float);
    cudaFuncSetAttribute(fused_kernel, cudaFuncAttributeMaxDynamicSharedMemorySize, smem_b);

    fused_kernel<<<NBLK, 256, smem_b>>>(adj, t, TE, nc, EE, W1, b1, W2, b2, Wc, bc, out);
}